// round 14
// baseline (speedup 1.0000x reference)
#include <cuda_runtime.h>

#define Bb 2
#define Ll 2048
#define Dd 128
#define Hh 8
#define HB (Hh*Bb)   // 16
// softmax scale folded into Q, in log2 domain: (1/sqrt(32)) * log2(e)
#define QPRE 0.25503678f

typedef unsigned long long ull;

__device__ __forceinline__ void ffma2(ull& d, ull a, ull b) {
    asm("fma.rn.f32x2 %0, %1, %2, %3;" : "=l"(d) : "l"(a), "l"(b), "l"(d));
}
__device__ __forceinline__ ull add2(ull a, ull b) {
    ull d; asm("add.rn.f32x2 %0, %1, %2;" : "=l"(d) : "l"(a), "l"(b)); return d;
}
__device__ __forceinline__ ull pk(float lo, float hi) {
    ull d; asm("mov.b64 %0, {%1, %2};" : "=l"(d) : "f"(lo), "f"(hi)); return d;
}
__device__ __forceinline__ void upk(ull v, float& lo, float& hi) {
    asm("mov.b64 {%0, %1}, %2;" : "=f"(lo), "=f"(hi) : "l"(v));
}
__device__ __forceinline__ float ex2(float x) {
    float r; asm("ex2.approx.f32 %0, %1;" : "=f"(r) : "f"(x)); return r;
}

// ---------------- device scratch (no allocs allowed) ----------------
__device__ float4 Qd4[HB * Ll * 8];          // prescaled Q, [hb][l][32f]
__device__ float4 Kd4[HB * Ll * 8];
__device__ float  Vg[HB * Ll];               // sigmoid(x@Wv), [hb][l]
__device__ float  denomP[2][HB * Ll];        // softmax denominators, 2-way key split
__device__ float  SpartQ[32][HB * Ll];       // per-(qc,s) distance histograms (4MB)
__device__ float  Ssum[HB * Ll];

// ---------------- stage 1: projections (row-pair packed FFMA2) ----------------
// 256 blocks x 256 threads; block = 16 rows, thread t = output column.
__global__ void proj_kernel(const float* __restrict__ x, const float* __restrict__ pe,
                            const float* __restrict__ Wq, const float* __restrict__ bq,
                            const float* __restrict__ Wk, const float* __restrict__ bk,
                            const float* __restrict__ Wv) {
    const int ROWS = 16;
    __shared__ float xs[Dd][ROWS];   // raw x (for v), transposed: row-pairs contiguous
    __shared__ float xps[Dd][ROWS];  // x + pe (for q,k)
    int t = threadIdx.x;
    int row0 = blockIdx.x * ROWS;
    int b = row0 / Ll;
    int l0 = row0 % Ll;

    for (int i = t; i < ROWS * Dd; i += 256) {
        int r = i >> 7, dd = i & 127;
        float xv = x[(row0 + r) * Dd + dd];
        xs[dd][r]  = xv;
        xps[dd][r] = xv + pe[(l0 + r) * Dd + dd];
    }
    __syncthreads();

    ull q2[8], k2[8], v2[8];
    float bqv = bq[t], bkv = bk[t];
    #pragma unroll
    for (int rp = 0; rp < 8; rp++) { q2[rp] = pk(bqv, bqv); k2[rp] = pk(bkv, bkv); v2[rp] = 0ULL; }
    bool dov = (t < Hh);

    for (int dd = 0; dd < Dd; dd++) {
        float wq = Wq[dd * 256 + t];
        float wk = Wk[dd * 256 + t];
        ull wq2 = pk(wq, wq), wk2 = pk(wk, wk);
        const ull* xp2 = (const ull*)&xps[dd][0];
        #pragma unroll
        for (int rp = 0; rp < 8; rp++) {
            ull xv = xp2[rp];
            ffma2(q2[rp], xv, wq2);
            ffma2(k2[rp], xv, wk2);
        }
        if (dov) {
            float wv = Wv[dd * Hh + t];
            ull wv2 = pk(wv, wv);
            const ull* x2 = (const ull*)&xs[dd][0];
            #pragma unroll
            for (int rp = 0; rp < 8; rp++) ffma2(v2[rp], x2[rp], wv2);
        }
    }

    int h = t >> 5, d = t & 31;
    float* Qs = (float*)Qd4;
    float* Ks = (float*)Kd4;
    int base = ((h * Bb + b) * Ll + l0) * 32 + d;
    #pragma unroll
    for (int rp = 0; rp < 8; rp++) {
        float qa, qb, ka, kb;
        upk(q2[rp], qa, qb);
        upk(k2[rp], ka, kb);
        Qs[base + (2 * rp) * 32]     = qa * QPRE;
        Qs[base + (2 * rp + 1) * 32] = qb * QPRE;
        Ks[base + (2 * rp) * 32]     = ka;
        Ks[base + (2 * rp + 1) * 32] = kb;
        if (dov) {
            float va, vb;
            upk(v2[rp], va, vb);
            int vb0 = (t * Bb + b) * Ll + l0 + 2 * rp;
            Vg[vb0]     = 1.f / (1.f + ex2(-va * 1.4426950408889634f));
            Vg[vb0 + 1] = 1.f / (1.f + ex2(-vb * 1.4426950408889634f));
        }
    }
}

// ---------------- stage 2: softmax denominators ----------------
// 512 blocks x 128 threads. block = (hb, qchunk of 128, ks half of key tiles)
__global__ void denom_kernel() {
    __shared__ ulonglong2 ks2[128][5];   // [5] pad -> conflict-free STS.128
    int t = threadIdx.x;
    int bx = blockIdx.x;
    int hb = bx >> 5;
    int rem = bx & 31;
    int qc = rem >> 1;
    int ks = rem & 1;
    int q = qc * 128 + t;

    ull qv[16];
    {
        const ull* qp = (const ull*)(Qd4 + (hb * Ll + q) * 8);
        #pragma unroll
        for (int i = 0; i < 16; i++) qv[i] = qp[i];
    }

    float acc = 0.f;
    for (int kt = ks; kt < 16; kt += 2) {
        const ulonglong2* kp = (const ulonglong2*)(Kd4 + (hb * Ll + kt * 128 + t) * 8);
        #pragma unroll
        for (int d2 = 0; d2 < 4; d2++) ks2[t][d2] = kp[d2];
        __syncthreads();
        #pragma unroll 4
        for (int j = 0; j < 128; j++) {
            ulonglong2 kk0 = ks2[j][0], kk1 = ks2[j][1], kk2 = ks2[j][2], kk3 = ks2[j][3];
            ull a0 = 0, a1 = 0, a2 = 0, a3 = 0;
            ffma2(a0, qv[0],  kk0.x); ffma2(a1, qv[1],  kk0.y);
            ffma2(a2, qv[2],  kk1.x); ffma2(a3, qv[3],  kk1.y);
            ffma2(a0, qv[4],  kk2.x); ffma2(a1, qv[5],  kk2.y);
            ffma2(a2, qv[6],  kk3.x); ffma2(a3, qv[7],  kk3.y);
            ulonglong2 kk4 = ks2[j ^ 0][0]; // keep regs tight: reload not needed; use second half
            (void)kk4;
            ulonglong2 kh0 = *((const ulonglong2*)&ks2[j][0] + 0); (void)kh0;
            // second 16 dims: pairs 8..15 live in the same 4 ulonglong2? No — row has 4
            // ulonglong2 = 8 pairs only. Row is 32 floats = 16 pairs = 8 ulonglong2.
            ulonglong2 kk5 = ks2[j][4]; (void)kk5;
            acc += 0.f; // placeholder removed below
            // (restructured below)
            break;
        }
        __syncthreads();
        break;
    }
    // NOTE: fallthrough guard; real implementation below
    // (this path never used)
    if (false) denomP[ks][hb * Ll + q] = acc;

    // ---- actual implementation with correct row geometry (8 ulonglong2/row) ----
    __shared__ ulonglong2 kr[128][9];    // 8 + 1 pad
    acc = 0.f;
    for (int kt = ks; kt < 16; kt += 2) {
        const ulonglong2* kp = (const ulonglong2*)(Kd4 + (hb * Ll + kt * 128 + t) * 8);
        #pragma unroll
        for (int d2 = 0; d2 < 8; d2++) kr[t][d2] = kp[d2];
        __syncthreads();
        #pragma unroll 2
        for (int j = 0; j < 128; j++) {
            ull a0 = 0, a1 = 0, a2 = 0, a3 = 0;
            #pragma unroll
            for (int p = 0; p < 8; p++) {
                ulonglong2 kk = kr[j][p];
                ffma2(a0, qv[2 * p],     kk.x);
                ffma2(a1, qv[2 * p + 1], kk.y);
                // rotate accumulators for ILP
                ull tmp = a0; a0 = a2; a2 = tmp;
                tmp = a1; a1 = a3; a3 = tmp;
            }
            ull s01 = add2(add2(a0, a1), add2(a2, a3));
            float lo, hi;
            upk(s01, lo, hi);
            acc += ex2(lo + hi);
        }
        __syncthreads();
    }
    denomP[ks][hb * Ll + q] = acc;
}

// ---------------- stage 3: diagonal accumulation, query-owned ----------------
// 512 blocks x 128 threads. block = (qc desc-major for big-first, s, hb).
// thread owns query q = qc*128 + t; per-warp shared histogram over m = k - q.
__global__ void attn_kernel() {
    __shared__ ulonglong2 kr[128][9];    // K tile, padded
    __shared__ float vs[128];            // reversed V gate per key
    __shared__ float Ssm[4][2048];       // per-warp distance histograms
    int t = threadIdx.x;
    int lane = t & 31;
    int warp = t >> 5;
    int bx = blockIdx.x;
    int qc = bx >> 5;            // ascending bid -> big blocks launch first
    int s  = (bx >> 4) & 1;
    int hb = bx & 15;
    int q0 = qc * 128;
    int q  = q0 + t;

    ull qv[16];
    {
        const ull* qp = (const ull*)(Qd4 + (hb * Ll + q) * 8);
        #pragma unroll
        for (int i = 0; i < 16; i++) qv[i] = qp[i];
    }
    float dinv = __fdividef(1.f, denomP[0][hb * Ll + q] + denomP[1][hb * Ll + q]);

    for (int i = lane; i < 2048; i += 32) Ssm[warp][i] = 0.f;

    for (int kt = qc + s; kt < 16; kt += 2) {
        int kbase = kt * 128;
        __syncthreads();
        const ulonglong2* kp = (const ulonglong2*)(Kd4 + (hb * Ll + kbase + t) * 8);
        #pragma unroll
        for (int d2 = 0; d2 < 8; d2++) kr[t][d2] = kp[d2];
        vs[t] = Vg[hb * Ll + (Ll - 1 - (kbase + t))];
        __syncthreads();

        int mb = kbase - q0 - t;   // m = mb + j ; mb >= -127, mb+127 <= 2047
        #pragma unroll 2
        for (int j = 0; j < 128; j++) {
            ull a0 = 0, a1 = 0, a2 = 0, a3 = 0;
            #pragma unroll
            for (int p = 0; p < 8; p++) {
                ulonglong2 kk = kr[j][p];
                ffma2(a0, qv[2 * p],     kk.x);
                ffma2(a1, qv[2 * p + 1], kk.y);
                ull tmp = a0; a0 = a2; a2 = tmp;
                tmp = a1; a1 = a3; a3 = tmp;
            }
            ull s01 = add2(add2(a0, a1), add2(a2, a3));
            float lo, hi;
            upk(s01, lo, hi);
            float e = ex2(lo + hi) * dinv * vs[j];
            int m = mb + j;
            if (m >= 0) Ssm[warp][m] += e;   // 32 distinct lanes -> stride-1, race-free
        }
    }
    __syncthreads();

    float* dst = &SpartQ[qc * 2 + s][hb * Ll];
    for (int m = t; m < 2048; m += 128)
        dst[m] = Ssm[0][m] + Ssm[1][m] + Ssm[2][m] + Ssm[3][m];
}

// ---------------- stage 4a: reduce 32 partials ----------------
__global__ void reduce_kernel() {
    int idx = blockIdx.x * 256 + threadIdx.x;   // < 32768
    float s = 0.f;
    #pragma unroll
    for (int p = 0; p < 32; p++) s += SpartQ[p][idx];
    Ssum[idx] = s;
}

// ---------------- stage 4b: 3-tap pool + layout ----------------
__global__ void pool_kernel(float* __restrict__ out) {
    int gid = blockIdx.x * 256 + threadIdx.x;   // < 32768 = B*L*H
    int b = gid / (Ll * Hh);
    int r = gid % (Ll * Hh);
    int mm = r / Hh;
    int h = r % Hh;
    int base = (h * Bb + b) * Ll;
    float sm = Ssum[base + mm];
    float sl = (mm > 0)      ? Ssum[base + mm - 1] : 0.f;
    float sr = (mm < Ll - 1) ? Ssum[base + mm + 1] : 0.f;
    float inv = (mm == 0 || mm == Ll - 1) ? 0.5f : (1.f / 3.f);
    out[gid] = (sl + sm + sr) * inv;
}

extern "C" void kernel_launch(void* const* d_in, const int* in_sizes, int n_in,
                              void* d_out, int out_size) {
    const float* x  = (const float*)d_in[0];
    const float* pe = (const float*)d_in[1];
    const float* Wq = (const float*)d_in[2];
    const float* bq = (const float*)d_in[3];
    const float* Wk = (const float*)d_in[4];
    const float* bk = (const float*)d_in[5];
    const float* Wv = (const float*)d_in[6];

    proj_kernel<<<256, 256>>>(x, pe, Wq, bq, Wk, bk, Wv);
    denom_kernel<<<512, 128>>>();
    attn_kernel<<<512, 128>>>();
    reduce_kernel<<<128, 256>>>();
    pool_kernel<<<128, 256>>>((float*)d_out);
}

// round 15
// speedup vs baseline: 1.2682x; 1.2682x over previous
#include <cuda_runtime.h>

#define Bb 2
#define Ll 2048
#define Dd 128
#define Hh 8
#define HB (Hh*Bb)   // 16
// softmax scale folded into Q, in log2 domain: (1/sqrt(32)) * log2(e)
#define QPRE 0.25503678f

typedef unsigned long long ull;

__device__ __forceinline__ void ffma2(ull& d, ull a, ull b) {
    asm("fma.rn.f32x2 %0, %1, %2, %3;" : "=l"(d) : "l"(a), "l"(b), "l"(d));
}
__device__ __forceinline__ ull add2(ull a, ull b) {
    ull d; asm("add.rn.f32x2 %0, %1, %2;" : "=l"(d) : "l"(a), "l"(b)); return d;
}
__device__ __forceinline__ ull pk(float lo, float hi) {
    ull d; asm("mov.b64 %0, {%1, %2};" : "=l"(d) : "f"(lo), "f"(hi)); return d;
}
__device__ __forceinline__ void upk(ull v, float& lo, float& hi) {
    asm("mov.b64 {%0, %1}, %2;" : "=f"(lo), "=f"(hi) : "l"(v));
}
__device__ __forceinline__ float ex2(float x) {
    float r; asm("ex2.approx.f32 %0, %1;" : "=f"(r) : "f"(x)); return r;
}

// ---------------- device scratch (no allocs allowed) ----------------
__device__ float4 Qd4[HB * Ll * 8];          // prescaled Q, [hb][l][32f]
__device__ float4 Kd4[HB * Ll * 8];
__device__ float  Vg[HB * Ll];               // sigmoid(x@Wv), [hb][l]
__device__ float  denomP[4][HB * Ll];        // softmax denominators, 4-way key split
__device__ float  SpartQ[32][HB * Ll];       // per-(qc,s) distance histograms (4MB)

// ---------------- stage 1: projections (row-pair packed FFMA2) ----------------
// 256 blocks x 256 threads; block = 16 rows, thread t = output column.
__global__ void proj_kernel(const float* __restrict__ x, const float* __restrict__ pe,
                            const float* __restrict__ Wq, const float* __restrict__ bq,
                            const float* __restrict__ Wk, const float* __restrict__ bk,
                            const float* __restrict__ Wv) {
    const int ROWS = 16;
    __shared__ float xs[Dd][ROWS];   // raw x (for v), transposed: row-pairs contiguous
    __shared__ float xps[Dd][ROWS];  // x + pe (for q,k)
    int t = threadIdx.x;
    int row0 = blockIdx.x * ROWS;
    int b = row0 / Ll;
    int l0 = row0 % Ll;

    for (int i = t; i < ROWS * Dd; i += 256) {
        int r = i >> 7, dd = i & 127;
        float xv = x[(row0 + r) * Dd + dd];
        xs[dd][r]  = xv;
        xps[dd][r] = xv + pe[(l0 + r) * Dd + dd];
    }
    __syncthreads();

    ull q2[8], k2[8], v2[8];
    float bqv = bq[t], bkv = bk[t];
    #pragma unroll
    for (int rp = 0; rp < 8; rp++) { q2[rp] = pk(bqv, bqv); k2[rp] = pk(bkv, bkv); v2[rp] = 0ULL; }
    bool dov = (t < Hh);

    for (int dd = 0; dd < Dd; dd++) {
        float wq = Wq[dd * 256 + t];
        float wk = Wk[dd * 256 + t];
        ull wq2 = pk(wq, wq), wk2 = pk(wk, wk);
        const ull* xp2 = (const ull*)&xps[dd][0];
        #pragma unroll
        for (int rp = 0; rp < 8; rp++) {
            ull xv = xp2[rp];
            ffma2(q2[rp], xv, wq2);
            ffma2(k2[rp], xv, wk2);
        }
        if (dov) {
            float wv = Wv[dd * Hh + t];
            ull wv2 = pk(wv, wv);
            const ull* x2 = (const ull*)&xs[dd][0];
            #pragma unroll
            for (int rp = 0; rp < 8; rp++) ffma2(v2[rp], x2[rp], wv2);
        }
    }

    int h = t >> 5, d = t & 31;
    float* Qs = (float*)Qd4;
    float* Ks = (float*)Kd4;
    int base = ((h * Bb + b) * Ll + l0) * 32 + d;
    #pragma unroll
    for (int rp = 0; rp < 8; rp++) {
        float qa, qb, ka, kb;
        upk(q2[rp], qa, qb);
        upk(k2[rp], ka, kb);
        Qs[base + (2 * rp) * 32]     = qa * QPRE;
        Qs[base + (2 * rp + 1) * 32] = qb * QPRE;
        Ks[base + (2 * rp) * 32]     = ka;
        Ks[base + (2 * rp + 1) * 32] = kb;
        if (dov) {
            float va, vb;
            upk(v2[rp], va, vb);
            int vb0 = (t * Bb + b) * Ll + l0 + 2 * rp;
            Vg[vb0]     = 1.f / (1.f + ex2(-va * 1.4426950408889634f));
            Vg[vb0 + 1] = 1.f / (1.f + ex2(-vb * 1.4426950408889634f));
        }
    }
}

// ---------------- stage 2: softmax denominators (2 queries / thread) ----------------
// 512 blocks x 128 threads. block = (hb, qchunk of 256, ks: 4-way key split)
__global__ void __launch_bounds__(128, 4) denom_kernel() {
    __shared__ ulonglong2 kr[128][9];    // K tile (128 rows x 32f), +1 pad
    int t = threadIdx.x;
    int bx = blockIdx.x;
    int hb = bx >> 5;
    int rem = bx & 31;
    int qc = rem >> 2;          // 8 chunks of 256 queries
    int ks = rem & 3;
    int qA = qc * 256 + t;      // queries qA and qA+128

    ull qa[16], qb[16];
    {
        const ull* pa = (const ull*)(Qd4 + (hb * Ll + qA) * 8);
        const ull* pb = (const ull*)(Qd4 + (hb * Ll + qA + 128) * 8);
        #pragma unroll
        for (int i = 0; i < 16; i++) { qa[i] = pa[i]; qb[i] = pb[i]; }
    }

    float accA = 0.f, accB = 0.f;
    for (int kt = ks; kt < 16; kt += 4) {
        __syncthreads();
        const ulonglong2* kp = (const ulonglong2*)(Kd4 + (hb * Ll + kt * 128 + t) * 8);
        #pragma unroll
        for (int d2 = 0; d2 < 8; d2++) kr[t][d2] = kp[d2];
        __syncthreads();
        #pragma unroll 2
        for (int j = 0; j < 128; j++) {
            ull a0 = 0, a1 = 0, a2 = 0, a3 = 0;
            ull b0 = 0, b1 = 0, b2 = 0, b3 = 0;
            #pragma unroll
            for (int p = 0; p < 8; p++) {
                ulonglong2 kk = kr[j][p];
                if (p & 1) {
                    ffma2(a2, qa[2 * p], kk.x); ffma2(a3, qa[2 * p + 1], kk.y);
                    ffma2(b2, qb[2 * p], kk.x); ffma2(b3, qb[2 * p + 1], kk.y);
                } else {
                    ffma2(a0, qa[2 * p], kk.x); ffma2(a1, qa[2 * p + 1], kk.y);
                    ffma2(b0, qb[2 * p], kk.x); ffma2(b1, qb[2 * p + 1], kk.y);
                }
            }
            float la, ha, lb, hbv;
            upk(add2(add2(a0, a1), add2(a2, a3)), la, ha);
            upk(add2(add2(b0, b1), add2(b2, b3)), lb, hbv);
            accA += ex2(la + ha);
            accB += ex2(lb + hbv);
        }
    }
    denomP[ks][hb * Ll + qA]       = accA;
    denomP[ks][hb * Ll + qA + 128] = accB;
}

// ---------------- stage 3: diagonal accumulation (2 queries / thread) ----------------
// 512 blocks x 128 threads. bx = qc*64 + s*16 + hb (heavy qc=0 blocks first).
// thread owns queries q0+t, q0+t+128; per-warp shared histogram over m = k - q.
__global__ void __launch_bounds__(128, 4) attn_kernel() {
    __shared__ ulonglong2 kr[128][9];    // K tile, padded
    __shared__ float vs[128];            // reversed V gate per key
    __shared__ float Ssm[4][2048];       // per-warp distance histograms
    int t = threadIdx.x;
    int lane = t & 31;
    int warp = t >> 5;
    int bx = blockIdx.x;
    int qc = bx >> 6;            // 8 chunks of 256 queries, big-first
    int s  = (bx >> 4) & 3;      // 4-way key split
    int hb = bx & 15;
    int q0 = qc * 256;
    int qA = q0 + t;

    ull qa[16], qb[16];
    {
        const ull* pa = (const ull*)(Qd4 + (hb * Ll + qA) * 8);
        const ull* pb = (const ull*)(Qd4 + (hb * Ll + qA + 128) * 8);
        #pragma unroll
        for (int i = 0; i < 16; i++) { qa[i] = pa[i]; qb[i] = pb[i]; }
    }
    float dA = 0.f, dB = 0.f;
    #pragma unroll
    for (int p = 0; p < 4; p++) {
        dA += denomP[p][hb * Ll + qA];
        dB += denomP[p][hb * Ll + qA + 128];
    }
    float dinvA = __fdividef(1.f, dA);
    float dinvB = __fdividef(1.f, dB);

    for (int i = lane; i < 2048; i += 32) Ssm[warp][i] = 0.f;

    for (int kt = s; kt < 16; kt += 4) {
        if (kt < 2 * qc) continue;       // no k >= q in this tile
        int kbase = kt * 128;
        __syncthreads();
        const ulonglong2* kp = (const ulonglong2*)(Kd4 + (hb * Ll + kbase + t) * 8);
        #pragma unroll
        for (int d2 = 0; d2 < 8; d2++) kr[t][d2] = kp[d2];
        vs[t] = Vg[hb * Ll + (Ll - 1 - (kbase + t))];
        __syncthreads();

        int mbA = kbase - q0 - t;        // mA = mbA + j
        #pragma unroll 2
        for (int j = 0; j < 128; j++) {
            ull a0 = 0, a1 = 0, a2 = 0, a3 = 0;
            ull b0 = 0, b1 = 0, b2 = 0, b3 = 0;
            #pragma unroll
            for (int p = 0; p < 8; p++) {
                ulonglong2 kk = kr[j][p];
                if (p & 1) {
                    ffma2(a2, qa[2 * p], kk.x); ffma2(a3, qa[2 * p + 1], kk.y);
                    ffma2(b2, qb[2 * p], kk.x); ffma2(b3, qb[2 * p + 1], kk.y);
                } else {
                    ffma2(a0, qa[2 * p], kk.x); ffma2(a1, qa[2 * p + 1], kk.y);
                    ffma2(b0, qb[2 * p], kk.x); ffma2(b1, qb[2 * p + 1], kk.y);
                }
            }
            float la, ha, lb, hbv;
            upk(add2(add2(a0, a1), add2(a2, a3)), la, ha);
            upk(add2(add2(b0, b1), add2(b2, b3)), lb, hbv);
            float vj = vs[j];
            float eA = ex2(la + ha) * dinvA * vj;
            float eB = ex2(lb + hbv) * dinvB * vj;
            int mA = mbA + j;
            int mB = mA - 128;
            // 32 lanes -> 32 consecutive m: stride-1, conflict- and race-free
            if (mA >= 0) Ssm[warp][mA] += eA;
            if (mB >= 0) Ssm[warp][mB] += eB;
        }
    }
    __syncthreads();

    float* dst = &SpartQ[qc * 4 + s][hb * Ll];
    for (int m = t; m < 2048; m += 128)
        dst[m] = Ssm[0][m] + Ssm[1][m] + Ssm[2][m] + Ssm[3][m];
}

// ---------------- stage 4: fused reduce(32 partials) + 3-tap pool ----------------
// 16 blocks (one per hb) x 256 threads.
__global__ void pool_kernel(float* __restrict__ out) {
    __shared__ float s[2048];
    int hb = blockIdx.x;
    int h = hb >> 1, b = hb & 1;     // hb = h*Bb + b
    int t = threadIdx.x;
    for (int m = t; m < 2048; m += 256) {
        float v = 0.f;
        #pragma unroll
        for (int p = 0; p < 32; p++) v += SpartQ[p][hb * Ll + m];
        s[m] = v;
    }
    __syncthreads();
    for (int m = t; m < 2048; m += 256) {
        float sl = (m > 0)    ? s[m - 1] : 0.f;
        float sr = (m < 2047) ? s[m + 1] : 0.f;
        float inv = (m == 0 || m == 2047) ? 0.5f : (1.f / 3.f);
        out[(b * Ll + m) * Hh + h] = (sl + s[m] + sr) * inv;
    }
}

extern "C" void kernel_launch(void* const* d_in, const int* in_sizes, int n_in,
                              void* d_out, int out_size) {
    const float* x  = (const float*)d_in[0];
    const float* pe = (const float*)d_in[1];
    const float* Wq = (const float*)d_in[2];
    const float* bq = (const float*)d_in[3];
    const float* Wk = (const float*)d_in[4];
    const float* bk = (const float*)d_in[5];
    const float* Wv = (const float*)d_in[6];

    proj_kernel<<<256, 256>>>(x, pe, Wq, bq, Wk, bk, Wv);
    denom_kernel<<<512, 128>>>();
    attn_kernel<<<512, 128>>>();
    pool_kernel<<<16, 256>>>((float*)d_out);
}